// round 15
// baseline (speedup 1.0000x reference)
#include <cuda_runtime.h>
#include <cuda_fp16.h>
#include <math.h>

#define NNODES 500000
#define FIN 16
#define HID 8
#define NCLS 2

// ---------------- device scratch ----------------
__device__ int     g_cnt  [NNODES];           // in-degree counter (excl. self-loop)
__device__ float   g_dinv [NNODES];           // deg^{-1/2}
__device__ __half2 g_uh   [NNODES * 4];       // unnormalized x@W1, f16 (8MB)
__device__ __half2 g_p1h  [NNODES * 4];       // (x@W1)*dinv, f16 (messages + self)
__device__ __half2 g_agg1h[NNODES * 4];       // layer-1 accumulator, f16
__device__ __half  g_p2dh [NNODES];           // scalar delta message, f16 (1MB)
__device__ float   g_agg2 [NNODES];           // layer-2 accumulator (f32 scalar)

// ---------------------------------------------------------------------------
__device__ __forceinline__ void red_add_v4h2(void* p, uint4 v) {
    asm volatile("red.global.add.noftz.v4.f16x2 [%0], {%1,%2,%3,%4};"
                 :: "l"(p), "r"(v.x), "r"(v.y), "r"(v.z), "r"(v.w) : "memory");
}
__device__ __forceinline__ void red_add_f(float* p, float v) {
    asm volatile("red.global.add.f32 [%0], %1;" :: "l"(p), "f"(v) : "memory");
}
__device__ __forceinline__ void red_add_s32(int* p, int v) {
    asm volatile("red.global.add.s32 [%0], %1;" :: "l"(p), "r"(v) : "memory");
}

// ---------------------------------------------------------------------------
// K0: init — zero cnt, agg1h, agg2 (R12's known-good streaming form)
// ---------------------------------------------------------------------------
__global__ void k_init(int n) {
    int i = blockIdx.x * blockDim.x + threadIdx.x;
    if (i >= n) return;
    ((uint4*)g_agg1h)[i] = make_uint4(0u, 0u, 0u, 0u);
    g_agg2[i] = 0.0f;
    g_cnt[i]  = 0;
}

// ---------------------------------------------------------------------------
// K1: degree + overlapped GEMM, BLOCK-specialized roles.
//     Blocks [0, ge4):      cnt[col] += 1, 4 edges/thread (LTS-atomic bound)
//     Blocks [ge4, +gn):    u[i] = f16(x[i] @ W1)        (DRAM-stream bound)
//     Different blocks -> different SM slots -> pipe-level overlap, no
//     per-thread serialization (R13/R14 lesson).
// ---------------------------------------------------------------------------
__global__ void k_deg_u(const int* __restrict__ col,
                        const float* __restrict__ x,
                        const float* __restrict__ W1,
                        int e4, int n, int edge_blocks) {
    if (blockIdx.x < (unsigned)edge_blocks) {
        int t = blockIdx.x * blockDim.x + threadIdx.x;
        if (t >= e4) return;
        int4 c = ((const int4*)col)[t];
        red_add_s32(&g_cnt[c.x], 1);
        red_add_s32(&g_cnt[c.y], 1);
        red_add_s32(&g_cnt[c.z], 1);
        red_add_s32(&g_cnt[c.w], 1);
    } else {
        __shared__ float sW1[FIN * HID];
        for (int k = threadIdx.x; k < FIN * HID; k += blockDim.x) sW1[k] = W1[k];
        __syncthreads();

        int i = (blockIdx.x - edge_blocks) * blockDim.x + threadIdx.x;
        if (i >= n) return;

        const float4* xr = (const float4*)(x + (size_t)i * FIN);
        float xv[FIN];
        #pragma unroll
        for (int q = 0; q < 4; q++) {
            float4 v = xr[q];
            xv[q*4+0] = v.x; xv[q*4+1] = v.y; xv[q*4+2] = v.z; xv[q*4+3] = v.w;
        }
        float h[HID];
        #pragma unroll
        for (int j = 0; j < HID; j++) h[j] = 0.f;
        #pragma unroll
        for (int k = 0; k < FIN; k++) {
            float xk = xv[k];
            #pragma unroll
            for (int j = 0; j < HID; j++) h[j] = fmaf(xk, sW1[k*HID + j], h[j]);
        }
        __half2 hh[4];
        #pragma unroll
        for (int q = 0; q < 4; q++)
            hh[q] = __floats2half2_rn(h[2*q], h[2*q+1]);
        ((uint4*)(g_uh + (size_t)i * 4))[0] = *(uint4*)hh;
    }
}

// ---------------------------------------------------------------------------
// K2: thin normalize — dinv = rsqrt(1+cnt); p1h = f16(u * dinv).
//     Reads 8MB u(f16) + 2MB cnt, all L2-resident.
// ---------------------------------------------------------------------------
__global__ void k_p1b(int n) {
    int i = blockIdx.x * blockDim.x + threadIdx.x;
    if (i >= n) return;
    float d = rsqrtf(1.0f + (float)g_cnt[i]);
    g_dinv[i] = d;
    uint4 uu = ((const uint4*)(g_uh + (size_t)i * 4))[0];
    __half2* uh = (__half2*)&uu;
    __half2 hh[4];
    #pragma unroll
    for (int q = 0; q < 4; q++) {
        float2 f = __half22float2(uh[q]);
        hh[q] = __floats2half2_rn(f.x * d, f.y * d);
    }
    ((uint4*)(g_p1h + (size_t)i * 4))[0] = *(uint4*)hh;
}

// ---------------------------------------------------------------------------
// K3: edge scatter, layer 1 — 16B f16 gather + ONE v4.f16x2 RED;
//     2 edges/thread (best measured geometry: 64.4us, 22 regs)
// ---------------------------------------------------------------------------
__global__ void k_scatter1(const int* __restrict__ row,
                           const int* __restrict__ col, int e2) {
    int t = blockIdx.x * blockDim.x + threadIdx.x;
    if (t >= e2) return;
    int2 r2 = ((const int2*)row)[t];
    int2 c2 = ((const int2*)col)[t];

    uint4 m0 = __ldg((const uint4*)(g_p1h + (size_t)r2.x * 4));
    uint4 m1 = __ldg((const uint4*)(g_p1h + (size_t)r2.y * 4));

    red_add_v4h2(g_agg1h + (size_t)c2.x * 4, m0);
    red_add_v4h2(g_agg1h + (size_t)c2.y * 4, m1);
}

// ---------------------------------------------------------------------------
// K4: per-node — h = relu(d*(agg1+p1)+b1); p2d = f16((h @ (W2c1-W2c0)) * d)
// ---------------------------------------------------------------------------
__global__ void k_layer1(const float* __restrict__ b1,
                         const float* __restrict__ W2, int n) {
    __shared__ float sWd[HID];
    __shared__ float sb1[HID];
    if (threadIdx.x < HID) {
        sWd[threadIdx.x] = W2[threadIdx.x * NCLS + 1] - W2[threadIdx.x * NCLS + 0];
        sb1[threadIdx.x] = b1[threadIdx.x];
    }
    __syncthreads();

    int i = blockIdx.x * blockDim.x + threadIdx.x;
    if (i >= n) return;

    float d = g_dinv[i];
    uint4 au = ((const uint4*)(g_agg1h + (size_t)i * 4))[0];
    uint4 pu = ((const uint4*)(g_p1h   + (size_t)i * 4))[0];
    __half2* ah = (__half2*)&au;
    __half2* ph = (__half2*)&pu;

    float zd = 0.f;
    #pragma unroll
    for (int q = 0; q < 4; q++) {
        float2 a = __half22float2(ah[q]);
        float2 p = __half22float2(ph[q]);
        float h0 = fmaxf(d * (a.x + p.x) + sb1[2*q],   0.f);
        float h1 = fmaxf(d * (a.y + p.y) + sb1[2*q+1], 0.f);
        zd = fmaf(h0, sWd[2*q],   zd);
        zd = fmaf(h1, sWd[2*q+1], zd);
    }
    g_p2dh[i] = __float2half_rn(zd * d);
}

// ---------------------------------------------------------------------------
// K5: edge scatter, layer 2 — f16 scalar gather (1MB working set) + f32 RED;
//     4 edges/thread
// ---------------------------------------------------------------------------
__global__ void k_scatter2(const int* __restrict__ row,
                           const int* __restrict__ col, int e4) {
    int t = blockIdx.x * blockDim.x + threadIdx.x;
    if (t >= e4) return;
    int4 r = ((const int4*)row)[t];
    int4 c = ((const int4*)col)[t];

    float v0 = __half2float(__ldg(&g_p2dh[r.x]));
    float v1 = __half2float(__ldg(&g_p2dh[r.y]));
    float v2 = __half2float(__ldg(&g_p2dh[r.z]));
    float v3 = __half2float(__ldg(&g_p2dh[r.w]));

    red_add_f(&g_agg2[c.x], v0);
    red_add_f(&g_agg2[c.y], v1);
    red_add_f(&g_agg2[c.z], v2);
    red_add_f(&g_agg2[c.w], v3);
}

// ---------------------------------------------------------------------------
// K6: per-node — delta = d*(agg2+p2d)+(b2[1]-b2[0]); stable 2-class log_softmax
// ---------------------------------------------------------------------------
__global__ void k_out(const float* __restrict__ b2, float* __restrict__ out, int n) {
    int i = blockIdx.x * blockDim.x + threadIdx.x;
    if (i >= n) return;
    float d  = g_dinv[i];
    float bd = __ldg(b2 + 1) - __ldg(b2 + 0);
    float self = __half2float(g_p2dh[i]);
    float delta = d * (g_agg2[i] + self) + bd;               // o1 - o0
    float sp = fmaxf(delta, 0.f) + log1pf(expf(-fabsf(delta)));
    ((float2*)out)[i] = make_float2(-sp, delta - sp);
}

// ---------------------------------------------------------------------------
extern "C" void kernel_launch(void* const* d_in, const int* in_sizes, int n_in,
                              void* d_out, int out_size) {
    const float* x  = (const float*)d_in[0];
    const float* W1 = (const float*)d_in[1];
    const float* b1 = (const float*)d_in[2];
    const float* W2 = (const float*)d_in[3];
    const float* b2 = (const float*)d_in[4];
    const int*   ei = (const int*)  d_in[5];

    int n = in_sizes[0] / FIN;         // 500000
    int e = in_sizes[5] / 2;           // 8000000
    const int* row = ei;
    const int* col = ei + e;
    float* out = (float*)d_out;

    const int TB = 256;
    int gn  = (n + TB - 1) / TB;       // 1954 node blocks
    int e2  = e / 2;
    int e4  = e / 4;
    int ge2 = (e2 + TB - 1) / TB;
    int ge4 = (e4 + TB - 1) / TB;      // 7813 edge blocks

    k_init    <<<gn, TB>>>(n);
    k_deg_u   <<<ge4 + gn, TB>>>(col, x, W1, e4, n, ge4);
    k_p1b     <<<gn, TB>>>(n);
    k_scatter1<<<ge2, TB>>>(row, col, e2);
    k_layer1  <<<gn, TB>>>(b1, W2, n);
    k_scatter2<<<ge4, TB>>>(row, col, e4);
    k_out     <<<gn, TB>>>(b2, out, n);
}

// round 16
// speedup vs baseline: 1.0019x; 1.0019x over previous
#include <cuda_runtime.h>
#include <cuda_fp16.h>
#include <math.h>

#define NNODES 500000
#define FIN 16
#define HID 8
#define NCLS 2

// ---------------- device scratch ----------------
__device__ int     g_cnt  [NNODES];           // in-degree counter (excl. self-loop)
__device__ float   g_dinv [NNODES];           // deg^{-1/2}
__device__ __half2 g_uh   [NNODES * 4];       // unnormalized x@W1, f16 (8MB)
__device__ __half2 g_p1h  [NNODES * 4];       // (x@W1)*dinv, f16 (messages + self)
__device__ __half2 g_agg1h[NNODES * 4];       // layer-1 accumulator, f16
__device__ __half  g_p2dh [NNODES];           // scalar delta message, f16 (1MB)
__device__ float   g_agg2 [NNODES];           // layer-2 accumulator (f32 scalar)

// ---------------------------------------------------------------------------
__device__ __forceinline__ void red_add_v4h2(void* p, uint4 v) {
    asm volatile("red.global.add.noftz.v4.f16x2 [%0], {%1,%2,%3,%4};"
                 :: "l"(p), "r"(v.x), "r"(v.y), "r"(v.z), "r"(v.w) : "memory");
}
__device__ __forceinline__ void red_add_f(float* p, float v) {
    asm volatile("red.global.add.f32 [%0], %1;" :: "l"(p), "f"(v) : "memory");
}
__device__ __forceinline__ void red_add_s32(int* p, int v) {
    asm volatile("red.global.add.s32 [%0], %1;" :: "l"(p), "r"(v) : "memory");
}

// ---------------------------------------------------------------------------
// K0: init — zero cnt ONLY (2MB, uint4); accumulator zeroing moved into
//     k_deg_u's node blocks (safe: agg1h/agg2 first touched in scatter1/2)
// ---------------------------------------------------------------------------
__global__ void k_zero_cnt(int n4) {
    int i = blockIdx.x * blockDim.x + threadIdx.x;
    if (i < n4) ((uint4*)g_cnt)[i] = make_uint4(0u, 0u, 0u, 0u);
}

// ---------------------------------------------------------------------------
// K1: degree + overlapped GEMM + accumulator zeroing, BLOCK-specialized.
//     Blocks [0, edge_blocks):  cnt[col] += 1, 4 edges/thread (LTS-atomic bound)
//     Blocks [edge_blocks, +gn): u[i] = f16(x[i] @ W1)  AND zero agg1h/agg2
//     (DRAM-stream bound; store slots idle → zeroing rides free here)
// ---------------------------------------------------------------------------
__global__ void k_deg_u(const int* __restrict__ col,
                        const float* __restrict__ x,
                        const float* __restrict__ W1,
                        int e4, int n, int edge_blocks) {
    if (blockIdx.x < (unsigned)edge_blocks) {
        int t = blockIdx.x * blockDim.x + threadIdx.x;
        if (t >= e4) return;
        int4 c = __ldg((const int4*)col + t);
        red_add_s32(&g_cnt[c.x], 1);
        red_add_s32(&g_cnt[c.y], 1);
        red_add_s32(&g_cnt[c.z], 1);
        red_add_s32(&g_cnt[c.w], 1);
    } else {
        __shared__ float sW1[FIN * HID];
        for (int k = threadIdx.x; k < FIN * HID; k += blockDim.x) sW1[k] = W1[k];
        __syncthreads();

        int i = (blockIdx.x - edge_blocks) * blockDim.x + threadIdx.x;
        if (i >= n) return;

        // zero accumulators (16B + 4B per node) — hidden under DRAM reads
        ((uint4*)g_agg1h)[i] = make_uint4(0u, 0u, 0u, 0u);
        g_agg2[i] = 0.0f;

        const float4* xr = (const float4*)(x + (size_t)i * FIN);
        float xv[FIN];
        #pragma unroll
        for (int q = 0; q < 4; q++) {
            float4 v = xr[q];
            xv[q*4+0] = v.x; xv[q*4+1] = v.y; xv[q*4+2] = v.z; xv[q*4+3] = v.w;
        }
        float h[HID];
        #pragma unroll
        for (int j = 0; j < HID; j++) h[j] = 0.f;
        #pragma unroll
        for (int k = 0; k < FIN; k++) {
            float xk = xv[k];
            #pragma unroll
            for (int j = 0; j < HID; j++) h[j] = fmaf(xk, sW1[k*HID + j], h[j]);
        }
        __half2 hh[4];
        #pragma unroll
        for (int q = 0; q < 4; q++)
            hh[q] = __floats2half2_rn(h[2*q], h[2*q+1]);
        ((uint4*)(g_uh + (size_t)i * 4))[0] = *(uint4*)hh;
    }
}

// ---------------------------------------------------------------------------
// K2: thin normalize — dinv = rsqrt(1+cnt); p1h = f16(u * dinv).
// ---------------------------------------------------------------------------
__global__ void k_p1b(int n) {
    int i = blockIdx.x * blockDim.x + threadIdx.x;
    if (i >= n) return;
    float d = rsqrtf(1.0f + (float)g_cnt[i]);
    g_dinv[i] = d;
    uint4 uu = ((const uint4*)(g_uh + (size_t)i * 4))[0];
    __half2* uh = (__half2*)&uu;
    __half2 hh[4];
    #pragma unroll
    for (int q = 0; q < 4; q++) {
        float2 f = __half22float2(uh[q]);
        hh[q] = __floats2half2_rn(f.x * d, f.y * d);
    }
    ((uint4*)(g_p1h + (size_t)i * 4))[0] = *(uint4*)hh;
}

// ---------------------------------------------------------------------------
// K3: edge scatter, layer 1 — 16B f16 gather + ONE v4.f16x2 RED;
//     2 edges/thread (best measured geometry: ~64.3us, 22 regs)
// ---------------------------------------------------------------------------
__global__ void k_scatter1(const int* __restrict__ row,
                           const int* __restrict__ col, int e2) {
    int t = blockIdx.x * blockDim.x + threadIdx.x;
    if (t >= e2) return;
    int2 r2 = __ldg((const int2*)row + t);
    int2 c2 = __ldg((const int2*)col + t);

    uint4 m0 = __ldg((const uint4*)(g_p1h + (size_t)r2.x * 4));
    uint4 m1 = __ldg((const uint4*)(g_p1h + (size_t)r2.y * 4));

    red_add_v4h2(g_agg1h + (size_t)c2.x * 4, m0);
    red_add_v4h2(g_agg1h + (size_t)c2.y * 4, m1);
}

// ---------------------------------------------------------------------------
// K4: per-node — h = relu(d*(agg1+p1)+b1); p2d = f16((h @ (W2c1-W2c0)) * d)
// ---------------------------------------------------------------------------
__global__ void k_layer1(const float* __restrict__ b1,
                         const float* __restrict__ W2, int n) {
    __shared__ float sWd[HID];
    __shared__ float sb1[HID];
    if (threadIdx.x < HID) {
        sWd[threadIdx.x] = W2[threadIdx.x * NCLS + 1] - W2[threadIdx.x * NCLS + 0];
        sb1[threadIdx.x] = b1[threadIdx.x];
    }
    __syncthreads();

    int i = blockIdx.x * blockDim.x + threadIdx.x;
    if (i >= n) return;

    float d = g_dinv[i];
    uint4 au = ((const uint4*)(g_agg1h + (size_t)i * 4))[0];
    uint4 pu = ((const uint4*)(g_p1h   + (size_t)i * 4))[0];
    __half2* ah = (__half2*)&au;
    __half2* ph = (__half2*)&pu;

    float zd = 0.f;
    #pragma unroll
    for (int q = 0; q < 4; q++) {
        float2 a = __half22float2(ah[q]);
        float2 p = __half22float2(ph[q]);
        float h0 = fmaxf(d * (a.x + p.x) + sb1[2*q],   0.f);
        float h1 = fmaxf(d * (a.y + p.y) + sb1[2*q+1], 0.f);
        zd = fmaf(h0, sWd[2*q],   zd);
        zd = fmaf(h1, sWd[2*q+1], zd);
    }
    g_p2dh[i] = __float2half_rn(zd * d);
}

// ---------------------------------------------------------------------------
// K5: edge scatter, layer 2 — f16 scalar gather (1MB working set) + f32 RED;
//     4 edges/thread
// ---------------------------------------------------------------------------
__global__ void k_scatter2(const int* __restrict__ row,
                           const int* __restrict__ col, int e4) {
    int t = blockIdx.x * blockDim.x + threadIdx.x;
    if (t >= e4) return;
    int4 r = __ldg((const int4*)row + t);
    int4 c = __ldg((const int4*)col + t);

    float v0 = __half2float(__ldg(&g_p2dh[r.x]));
    float v1 = __half2float(__ldg(&g_p2dh[r.y]));
    float v2 = __half2float(__ldg(&g_p2dh[r.z]));
    float v3 = __half2float(__ldg(&g_p2dh[r.w]));

    red_add_f(&g_agg2[c.x], v0);
    red_add_f(&g_agg2[c.y], v1);
    red_add_f(&g_agg2[c.z], v2);
    red_add_f(&g_agg2[c.w], v3);
}

// ---------------------------------------------------------------------------
// K6: per-node — delta = d*(agg2+p2d)+(b2[1]-b2[0]); stable 2-class log_softmax
// ---------------------------------------------------------------------------
__global__ void k_out(const float* __restrict__ b2, float* __restrict__ out, int n) {
    int i = blockIdx.x * blockDim.x + threadIdx.x;
    if (i >= n) return;
    float d  = g_dinv[i];
    float bd = __ldg(b2 + 1) - __ldg(b2 + 0);
    float self = __half2float(g_p2dh[i]);
    float delta = d * (g_agg2[i] + self) + bd;               // o1 - o0
    float sp = fmaxf(delta, 0.f) + log1pf(expf(-fabsf(delta)));
    ((float2*)out)[i] = make_float2(-sp, delta - sp);
}

// ---------------------------------------------------------------------------
extern "C" void kernel_launch(void* const* d_in, const int* in_sizes, int n_in,
                              void* d_out, int out_size) {
    const float* x  = (const float*)d_in[0];
    const float* W1 = (const float*)d_in[1];
    const float* b1 = (const float*)d_in[2];
    const float* W2 = (const float*)d_in[3];
    const float* b2 = (const float*)d_in[4];
    const int*   ei = (const int*)  d_in[5];

    int n = in_sizes[0] / FIN;         // 500000
    int e = in_sizes[5] / 2;           // 8000000
    const int* row = ei;
    const int* col = ei + e;
    float* out = (float*)d_out;

    const int TB = 256;
    int gn  = (n + TB - 1) / TB;       // 1954 node blocks
    int n4  = n / 4;
    int gz  = (n4 + TB - 1) / TB;
    int e2  = e / 2;
    int e4  = e / 4;
    int ge2 = (e2 + TB - 1) / TB;
    int ge4 = (e4 + TB - 1) / TB;      // 7813 edge blocks

    k_zero_cnt<<<gz, TB>>>(n4);
    k_deg_u   <<<ge4 + gn, TB>>>(col, x, W1, e4, n, ge4);
    k_p1b     <<<gn, TB>>>(n);
    k_scatter1<<<ge2, TB>>>(row, col, e2);
    k_layer1  <<<gn, TB>>>(b1, W2, n);
    k_scatter2<<<ge4, TB>>>(row, col, e4);
    k_out     <<<gn, TB>>>(b2, out, n);
}